// round 11
// baseline (speedup 1.0000x reference)
#include <cuda_runtime.h>
#include <math.h>
#include <stdint.h>

// Problem constants
#define BATCH 2
#define NPTS 1024
#define NUM_BINS 22
#define TDIM 16
#define TSTRIDE 20           // padded table row stride (floats) for LDS conflicts
#define MAX_DIST 40.0f
#define LN_EPS 1e-5f

// ---------------------------------------------------------------------------
// Single fused kernel (one graph node), software-pipelined prologue:
//   1) warp 0 issues W/b/gamma/beta float4 loads (latency only, no consumer)
//   2) ALL threads run Phase A (per-j bin offset + scale -> smem) — hides (1)
//   3) threads 0..21 finish LN math + write table rows to smem
//   4) barrier; Phase B: 4 lanes/pair, LDS.64 broadcast + LDS.128 gather,
//      2 packed f32x2 muls, STG.128.
// Grid (N/256, N, B) = 8192 blocks of 256 (the measured-best shape).
// ---------------------------------------------------------------------------
__global__ __launch_bounds__(256)
void encode_kernel(const float* __restrict__ coords,
                   const float* __restrict__ conf,
                   const float* __restrict__ W,
                   const float* __restrict__ bb,
                   const float* __restrict__ gamma,
                   const float* __restrict__ beta,
                   float* __restrict__ out) {
    __shared__ float  sT[NUM_BINS * TSTRIDE];
    __shared__ float2 sP[256];    // (row byte-offset, scale) per local j

    const int tid    = threadIdx.x;
    const int i      = blockIdx.y;
    const int batch  = blockIdx.z;
    const int j_base = blockIdx.x * 256;

    // ---- Stage 1: issue table-input loads early (warp 0 only) ----
    float4 w0, w1, w2, w3, b0, b1, b2, b3, g0, g1, g2, g3, e0, e1, e2, e3;
    if (tid < 32) {
        const int bin = (tid < NUM_BINS) ? tid : (NUM_BINS - 1);
        const float4* W4 = (const float4*)(W + bin * TDIM);
        w0 = W4[0]; w1 = W4[1]; w2 = W4[2]; w3 = W4[3];
        const float4* B4 = (const float4*)bb;
        b0 = B4[0]; b1 = B4[1]; b2 = B4[2]; b3 = B4[3];
        const float4* G4 = (const float4*)gamma;
        g0 = G4[0]; g1 = G4[1]; g2 = G4[2]; g3 = G4[3];
        const float4* E4 = (const float4*)beta;
        e0 = E4[0]; e1 = E4[1]; e2 = E4[2]; e3 = E4[3];
    }

    // ---- Stage 2: Phase A (all threads; hides stage-1 latency) ----
    {
        const float* ci_ptr = coords + ((size_t)batch * NPTS + i) * 3;
        const float xi = ci_ptr[0], yi = ci_ptr[1], zi = ci_ptr[2];
        const float ci = conf[batch * NPTS + i];

        const int j = j_base + tid;
        const float* cj_ptr = coords + ((size_t)batch * NPTS + j) * 3;
        const float dx = xi - cj_ptr[0];
        const float dy = yi - cj_ptr[1];
        const float dz = zi - cj_ptr[2];
        const float cj = conf[batch * NPTS + j];

        const float dist = sqrtf(fmaf(dx, dx, fmaf(dy, dy, fmaf(dz, dz, 1e-8f))));
        const float inv_w = (float)(NUM_BINS - 1) / MAX_DIST;  // 21/40

        int bin;
        if (ci > 0.0f && cj > 0.0f) {
            bin = (int)(dist * inv_w) + 1;          // #edges strictly below dist
            bin = (bin > NUM_BINS - 2) ? (NUM_BINS - 2) : bin;
        } else {
            bin = NUM_BINS - 1;
        }
        sP[tid] = make_float2(__int_as_float(bin * (TSTRIDE * 4)),
                              fminf(ci, cj));
    }

    // ---- Stage 3: finish table build (threads 0..21, math only) ----
    if (tid < NUM_BINS) {
        float h[TDIM];
        h[0]=w0.x+b0.x; h[1]=w0.y+b0.y; h[2]=w0.z+b0.z; h[3]=w0.w+b0.w;
        h[4]=w1.x+b1.x; h[5]=w1.y+b1.y; h[6]=w1.z+b1.z; h[7]=w1.w+b1.w;
        h[8]=w2.x+b2.x; h[9]=w2.y+b2.y; h[10]=w2.z+b2.z; h[11]=w2.w+b2.w;
        h[12]=w3.x+b3.x; h[13]=w3.y+b3.y; h[14]=w3.z+b3.z; h[15]=w3.w+b3.w;
        float sum = 0.0f;
#pragma unroll
        for (int d = 0; d < TDIM; ++d) sum += h[d];
        const float mu = sum * (1.0f / TDIM);
        float var = 0.0f;
#pragma unroll
        for (int d = 0; d < TDIM; ++d) { const float c = h[d] - mu; var += c * c; }
        var *= (1.0f / TDIM);
        const float inv = rsqrtf(var + LN_EPS);
        const float gg[TDIM] = {g0.x,g0.y,g0.z,g0.w, g1.x,g1.y,g1.z,g1.w,
                                g2.x,g2.y,g2.z,g2.w, g3.x,g3.y,g3.z,g3.w};
        const float ee[TDIM] = {e0.x,e0.y,e0.z,e0.w, e1.x,e1.y,e1.z,e1.w,
                                e2.x,e2.y,e2.z,e2.w, e3.x,e3.y,e3.z,e3.w};
#pragma unroll
        for (int d = 0; d < TDIM; ++d) {
            const float v = (h[d] - mu) * inv * gg[d] + ee[d];
            sT[tid * TSTRIDE + d] = fmaxf(v, 0.0f);
        }
    }
    __syncthreads();

    // ---- Phase B: gather + scale + store ----
    const int p = tid >> 2;   // pair slot within 64
    const int k = tid & 3;    // which float4 of the 16-vector

    float* optr = out + (((size_t)batch * NPTS + i) * NPTS + j_base + p) * TDIM + k * 4;
    const char* tbase = (const char*)sT + k * 16;

#pragma unroll
    for (int it = 0; it < 4; ++it) {
        const float2 pk = sP[it * 64 + p];      // broadcast within 4-lane group
        const int   off = __float_as_int(pk.x);
        const float s   = pk.y;

        float4 v = *(const float4*)(tbase + off);

        // packed f32x2 multiplies: 2 instructions instead of 4
        uint64_t lo, hi, sv, rlo, rhi;
        asm("mov.b64 %0, {%1, %2};" : "=l"(sv) : "f"(s), "f"(s));
        asm("mov.b64 %0, {%1, %2};" : "=l"(lo) : "f"(v.x), "f"(v.y));
        asm("mov.b64 %0, {%1, %2};" : "=l"(hi) : "f"(v.z), "f"(v.w));
        asm("mul.rn.f32x2 %0, %1, %2;" : "=l"(rlo) : "l"(lo), "l"(sv));
        asm("mul.rn.f32x2 %0, %1, %2;" : "=l"(rhi) : "l"(hi), "l"(sv));
        float4 r;
        asm("mov.b64 {%0, %1}, %2;" : "=f"(r.x), "=f"(r.y) : "l"(rlo));
        asm("mov.b64 {%0, %1}, %2;" : "=f"(r.z), "=f"(r.w) : "l"(rhi));

        *(float4*)(optr + (size_t)it * 64 * TDIM) = r;
    }
}

// ---------------------------------------------------------------------------
// Launch: single kernel, single graph node.
// ---------------------------------------------------------------------------
extern "C" void kernel_launch(void* const* d_in, const int* in_sizes, int n_in,
                              void* d_out, int out_size) {
    const float* coords = (const float*)d_in[0];  // (B,N,3)
    const float* conf   = (const float*)d_in[1];  // (B,N)
    const float* W      = (const float*)d_in[2];  // (22,16)
    const float* b      = (const float*)d_in[3];  // (16,)
    const float* gamma  = (const float*)d_in[4];  // (16,)
    const float* beta   = (const float*)d_in[5];  // (16,)
    float* out = (float*)d_out;                   // (B,N,N,16)

    dim3 grid(NPTS / 256, NPTS, BATCH);
    encode_kernel<<<grid, 256>>>(coords, conf, W, b, gamma, beta, out);
}